// round 6
// baseline (speedup 1.0000x reference)
#include <cuda_runtime.h>

// MPSLayer:
//   out[b,:] = (prod_t x[b,t]) * w + bias,   w = 1^T * (A_0...A_{D-1}) * P
// K1 (fused, no intra-kernel waits):
//   blocks [0,nprod):  matrix-chain tree -> g_w  (atomic-elected reducers)
//   blocks [nprod,..): per-row products -> g_p via cp.async 4-deep pipeline
// K2: out = g_p * g_w + bias (float4-vectorized, guarded for p==0).

#define R   16
#define RR  256
#define TS  20
#define CHUNK 16
#define MAXG  16
#define DEPTH 4           // cp.async pipeline depth (chunks of 32 float4 / warp)

__device__ float g_part1[256 * RR];
__device__ float g_part2[MAXG * RR];
__device__ float g_w[4096];
__device__ float g_p[65536];
__device__ int   g_sync[MAXG + 1];

struct ChainSm {
    float S[CHUNK - 1][R * TS];
    float M[2][RR];
    float u[R];
    int   rank;
};
struct StreamSm {
    float4 buf[8][DEPTH][32];   // [warp][stage][lane]
};
union Sm { ChainSm chain; StreamSm stream; };

__device__ __forceinline__ void cp_async16(void* smem, const void* gmem) {
    unsigned sa = (unsigned)__cvta_generic_to_shared(smem);
    asm volatile("cp.async.cg.shared.global [%0], [%1], 16;\n" :: "r"(sa), "l"(gmem));
}
#define CP_COMMIT()  asm volatile("cp.async.commit_group;\n" ::: "memory")
#define CP_WAIT(n)   asm volatile("cp.async.wait_group %0;\n" :: "n"(n) : "memory")

// Ordered product of n (<=16) RxR matrices at base; result in sm->M[ret].
__device__ __forceinline__ int chain_prod(const float* __restrict__ base, int n,
                                          ChainSm* sm, int t, int i, int j) {
    __syncthreads();
    for (int s = 1; s < n; ++s)
        sm->S[s - 1][(t & 15) * TS + (t >> 4)] = base[(size_t)s * RR + t];
    sm->M[0][t] = base[t];
    __syncthreads();
    int cur = 0;
    for (int s = 1; s < n; ++s) {
        const float4* mrow = (const float4*)&sm->M[cur][i * R];
        const float4* bcol = (const float4*)&sm->S[s - 1][j * TS];
        float4 a0 = mrow[0], a1 = mrow[1], a2 = mrow[2], a3 = mrow[3];
        float4 b0 = bcol[0], b1 = bcol[1], b2 = bcol[2], b3 = bcol[3];
        float acc = a0.x * b0.x;
        acc = fmaf(a0.y, b0.y, acc); acc = fmaf(a0.z, b0.z, acc); acc = fmaf(a0.w, b0.w, acc);
        acc = fmaf(a1.x, b1.x, acc); acc = fmaf(a1.y, b1.y, acc);
        acc = fmaf(a1.z, b1.z, acc); acc = fmaf(a1.w, b1.w, acc);
        acc = fmaf(a2.x, b2.x, acc); acc = fmaf(a2.y, b2.y, acc);
        acc = fmaf(a2.z, b2.z, acc); acc = fmaf(a2.w, b2.w, acc);
        acc = fmaf(a3.x, b3.x, acc); acc = fmaf(a3.y, b3.y, acc);
        acc = fmaf(a3.z, b3.z, acc); acc = fmaf(a3.w, b3.w, acc);
        sm->M[cur ^ 1][t] = acc;
        cur ^= 1;
        __syncthreads();
    }
    return cur;
}

__global__ __launch_bounds__(256, 8)
void mps_fused(const float* __restrict__ x, const float* __restrict__ cores,
               const float* __restrict__ proj,
               int B, int D, int O, int nprod, int ngrp) {
    __shared__ Sm smu;
    const int t = threadIdx.x;

    if ((int)blockIdx.x < nprod) {
        // ---------------- chain producer path ----------------
        ChainSm* sm = &smu.chain;
        const int i = t >> 4, j = t & 15;
        const int start = blockIdx.x * CHUNK;
        const int n = min(CHUNK, D - start);
        int cur = chain_prod(cores + (size_t)start * RR, n, sm, t, i, j);
        g_part1[(size_t)blockIdx.x * RR + t] = sm->M[cur][t];
        __threadfence();
        const int grp = blockIdx.x >> 4;
        const int gsz = min(16, nprod - (grp << 4));
        if (t == 0) sm->rank = atomicAdd(&g_sync[grp], 1);
        __syncthreads();
        if (sm->rank == gsz - 1) {
            __threadfence();
            cur = chain_prod(g_part1 + (size_t)(grp << 4) * RR, gsz, sm, t, i, j);
            g_part2[(size_t)grp * RR + t] = sm->M[cur][t];
            __threadfence();
            if (t == 0) sm->rank = atomicAdd(&g_sync[MAXG], 1);
            __syncthreads();
            if (sm->rank == ngrp - 1) {
                __threadfence();
                cur = chain_prod(g_part2, ngrp, sm, t, i, j);
                if (t < R) {
                    float s = 0.0f;
#pragma unroll
                    for (int ii = 0; ii < R; ++ii) s += sm->M[cur][ii * R + t];
                    sm->u[t] = s;
                }
                __syncthreads();
                for (int o = t; o < O; o += 256) {
                    float s = 0.0f;
#pragma unroll
                    for (int k = 0; k < R; ++k)
                        s = fmaf(sm->u[k], proj[k * O + o], s);
                    g_w[o] = s;
                }
                if (t <= MAXG) g_sync[t] = 0;   // reset for next graph replay
            }
        }
        return;
    }

    // ---------------- streaming path: one warp per row, cp.async pipeline ----
    const int w = t >> 5, lane = t & 31;
    const int row = ((int)blockIdx.x - nprod) * 8 + w;
    if (row >= B) return;

    const float* xr = x + (size_t)row * D;
    float p = 1.0f;

    if ((D & 3) == 0) {
        const float4* src = (const float4*)xr;
        const int n4 = D >> 2;
        const int nchunk = n4 >> 5;                 // 32 float4 per chunk per warp
        float4 (*buf)[32] = smu.stream.buf[w];

#pragma unroll
        for (int c = 0; c < DEPTH; ++c) {
            if (c < nchunk) cp_async16(&buf[c][lane], &src[c * 32 + lane]);
            CP_COMMIT();
        }
        for (int c = 0; c < nchunk; ++c) {
            CP_WAIT(DEPTH - 1);                     // chunk c complete (empty-group trick)
            float4 v = buf[c & (DEPTH - 1)][lane];  // each lane touches only its own slot
            p *= v.x * v.y * v.z * v.w;
            const int nc = c + DEPTH;
            if (nc < nchunk) cp_async16(&buf[nc & (DEPTH - 1)][lane], &src[nc * 32 + lane]);
            CP_COMMIT();
        }
        for (int idx = (nchunk << 5) + lane; idx < n4; idx += 32) {  // leftover float4s
            float4 v = src[idx];
            p *= v.x * v.y * v.z * v.w;
        }
    } else {
        for (int idx = lane; idx < D; idx += 32) p *= xr[idx];
    }

#pragma unroll
    for (int o = 16; o; o >>= 1)
        p *= __shfl_xor_sync(0xffffffffu, p, o);
    if (lane == 0) g_p[row] = p;
}

__global__ void mps_combine_v4(const float* __restrict__ bias,
                               float* __restrict__ out, int B, int O4) {
    const int idx = blockIdx.x * blockDim.x + threadIdx.x;
    if (idx >= B * O4) return;
    const int b = idx / O4, o4 = idx - b * O4;
    const float p = g_p[b];
    const float4 w4 = ((const float4*)g_w)[o4];
    const float4 bs = ((const float4*)bias)[o4];
    float4 r;
    if (p == 0.0f) {
        r = bs;
    } else {
        r.x = fmaf(p, w4.x, bs.x); r.y = fmaf(p, w4.y, bs.y);
        r.z = fmaf(p, w4.z, bs.z); r.w = fmaf(p, w4.w, bs.w);
    }
    ((float4*)out)[idx] = r;
}

__global__ void mps_combine_sc(const float* __restrict__ bias,
                               float* __restrict__ out, int B, int O) {
    const int idx = blockIdx.x * blockDim.x + threadIdx.x;
    if (idx >= B * O) return;
    const int b = idx / O, o = idx - b * O;
    const float p = g_p[b];
    out[idx] = (p == 0.0f) ? bias[o] : fmaf(p, g_w[o], bias[o]);
}

extern "C" void kernel_launch(void* const* d_in, const int* in_sizes, int n_in,
                              void* d_out, int out_size) {
    const float* x     = (const float*)d_in[0];  // (B, D)
    const float* cores = (const float*)d_in[1];  // (D, 16, 16)
    const float* proj  = (const float*)d_in[2];  // (16, O)
    const float* bias  = (const float*)d_in[3];  // (O,)
    float* out = (float*)d_out;                  // (B, O)

    const int D = in_sizes[1] / RR;
    const int B = in_sizes[0] / D;
    const int O = in_sizes[3];

    int nprod = (D + CHUNK - 1) / CHUNK;         // 128 for D=2048
    if (nprod > 256) nprod = 256;
    const int ngrp = (nprod + 15) / 16;

    const int row_blocks = (B + 7) / 8;
    mps_fused<<<nprod + row_blocks, 256>>>(x, cores, proj, B, D, O, nprod, ngrp);

    if ((O & 3) == 0) {
        const int total4 = B * (O >> 2);
        mps_combine_v4<<<(total4 + 255) / 256, 256>>>(bias, out, B, O >> 2);
    } else {
        const int total = B * O;
        mps_combine_sc<<<(total + 255) / 256, 256>>>(bias, out, B, O);
    }
}